// round 5
// baseline (speedup 1.0000x reference)
#include <cuda_runtime.h>
#include <mma.h>

using namespace nvcuda;

#define NN 100000
#define NP 100032              // 1563 * 64, padded rows for unguarded GEMM stores
#define EE 1600000
#define DD 128
#define ET (EE + NN)

// ---------------- scratch (static device globals; no allocations) ----------
__device__ int   g_flag;           // nonzero => edge_index is int32
__device__ int   g_deg[NN];        // degree over row incl. self loop
__device__ int   g_cnt[NN];        // in-degree over col incl. self loop
__device__ int   g_off[NN + 1];    // CSR offsets by col
__device__ int   g_cur[NN];        // fill cursors
__device__ float g_dis[NN];        // deg^-0.5
__device__ float g_s[NN];          // s_i = sum_j norm_ij (for bias folding)
__device__ int2  g_edges[ET];      // (src, weight-as-bits), grouped by dst
__device__ float g_P[(size_t)NP * DD];  // projected features (GEMM out, pull in)
__device__ float g_H[(size_t)NN * DD];  // hidden features (pull out, GEMM in)

// ---------------- dtype handling --------------------------------------------
// If edge_index is int64, all high 32-bit words are zero (values in [0, 1e5)).
__global__ void k_detect(const int* __restrict__ ei32) {
    int t = threadIdx.x;
    if (t == 0) g_flag = 0;
    __syncthreads();
    int w = 0;
    for (int i = t; i < 4096; i += blockDim.x)
        w |= ei32[2 * i + 1];
    if (w != 0) atomicOr(&g_flag, 1);
}

__device__ __forceinline__ int ld_idx(const void* ei, long long pos, bool is32) {
    return is32 ? ((const int*)ei)[pos] : (int)((const long long*)ei)[pos];
}

// ---------------- preprocessing --------------------------------------------
__global__ void k_init() {
    int i = blockIdx.x * blockDim.x + threadIdx.x;
    if (i < NN) { g_deg[i] = 1; g_cnt[i] = 1; g_cur[i] = 0; g_s[i] = 0.f; }
}

__global__ void k_count(const void* __restrict__ ei) {
    int e = blockIdx.x * blockDim.x + threadIdx.x;
    bool is32 = (g_flag != 0);
    if (e < EE) {
        int r = ld_idx(ei, e, is32);
        int c = ld_idx(ei, (long long)EE + e, is32);
        if ((unsigned)r < NN && (unsigned)c < NN) {
            atomicAdd(&g_deg[r], 1);   // row (source)
            atomicAdd(&g_cnt[c], 1);   // col (target)
        }
    }
}

__global__ void k_dis() {
    int i = blockIdx.x * blockDim.x + threadIdx.x;
    if (i < NN) g_dis[i] = rsqrtf((float)g_deg[i]);
}

// exclusive scan of g_cnt -> g_off, single block of 1024 threads
__global__ __launch_bounds__(1024) void k_scan() {
    const int T = 1024;
    const int C = (NN + T - 1) / T;   // 98
    int t = threadIdx.x;
    int base = t * C;
    int s = 0;
    for (int j = 0; j < C; j++) { int idx = base + j; if (idx < NN) s += g_cnt[idx]; }
    __shared__ int ps[T];
    ps[t] = s;
    __syncthreads();
    for (int d = 1; d < T; d <<= 1) {
        int v = (t >= d) ? ps[t - d] : 0;
        __syncthreads();
        ps[t] += v;
        __syncthreads();
    }
    int run = ps[t] - s;  // exclusive prefix
    for (int j = 0; j < C; j++) {
        int idx = base + j;
        if (idx < NN) { g_off[idx] = run; run += g_cnt[idx]; }
    }
    if (t == T - 1) g_off[NN] = run;
}

// scatter edges (and self loops) into CSR-by-col with fused weights;
// also accumulate s_i = sum of weights per target (bias folding).
__global__ void k_fill(const void* __restrict__ ei) {
    int e = blockIdx.x * blockDim.x + threadIdx.x;
    bool is32 = (g_flag != 0);
    if (e < EE) {
        int r = ld_idx(ei, e, is32);
        int c = ld_idx(ei, (long long)EE + e, is32);
        if ((unsigned)r < NN && (unsigned)c < NN) {
            float w = g_dis[r] * g_dis[c];
            int pos = g_off[c] + atomicAdd(&g_cur[c], 1);
            g_edges[pos] = make_int2(r, __float_as_int(w));
            atomicAdd(&g_s[c], w);
        }
    } else if (e < ET) {
        int i = e - EE;
        float d = g_dis[i];
        float w = d * d;
        int pos = g_off[i] + atomicAdd(&g_cur[i], 1);
        g_edges[pos] = make_int2(i, __float_as_int(w));
        atomicAdd(&g_s[i], w);
    }
}

// ---------------- GEMM: g_P[N,128] = A[N,128] @ W^T  (no bias) -------------
// tf32 tensor cores with 3xTF32 error compensation.
// Block: 64 rows x 128 cols, 8 warps. Warp (mt, ng): m-tile 16 rows, 64 cols.
__device__ __forceinline__ float tf32_hi(float x) {
    return __uint_as_float(__float_as_uint(x) & 0xFFFFE000u);
}

template <bool USE_H>
__global__ __launch_bounds__(256) void k_gemm(const float* __restrict__ Ax,
                                              const float* __restrict__ Wm) {
    // rows padded to 24 floats (96B) so wmma pointers are 32B-aligned
    __shared__ __align__(32) float sAhi[64][24], sAlo[64][24];
    __shared__ __align__(32) float sWhi[128][24], sWlo[128][24];

    const float* __restrict__ A = USE_H ? (const float*)g_H : Ax;

    int t = threadIdx.x;
    int w = t >> 5;
    int mt = w & 3;        // m tile: rows mt*16..+15
    int ng = w >> 2;       // n group: cols ng*64..+63
    int rowBase = blockIdx.x * 64;

    wmma::fragment<wmma::accumulator, 16, 16, 8, float> acc[4];
#pragma unroll
    for (int i = 0; i < 4; i++) wmma::fill_fragment(acc[i], 0.f);

    for (int kt = 0; kt < 8; kt++) {       // BK = 16
        // A tile 64x16: 256 float4, one per thread
        {
            int r = t >> 2, c4 = t & 3;
            int gr = rowBase + r;
            float4 v = make_float4(0.f, 0.f, 0.f, 0.f);
            if (gr < NN)
                v = *(const float4*)(A + (size_t)gr * DD + kt * 16 + c4 * 4);
            float4 hi = make_float4(tf32_hi(v.x), tf32_hi(v.y), tf32_hi(v.z), tf32_hi(v.w));
            float4 lo = make_float4(v.x - hi.x, v.y - hi.y, v.z - hi.z, v.w - hi.w);
            *(float4*)&sAhi[r][c4 * 4] = hi;
            *(float4*)&sAlo[r][c4 * 4] = lo;
        }
        // W tile 128x16: 512 float4, two per thread. sW[n][k] = W[n][kt*16+k]
#pragma unroll
        for (int i = 0; i < 2; i++) {
            int idx = t + i * 256;
            int n = idx >> 2, k4 = idx & 3;
            float4 v = *(const float4*)(Wm + (size_t)n * DD + kt * 16 + k4 * 4);
            float4 hi = make_float4(tf32_hi(v.x), tf32_hi(v.y), tf32_hi(v.z), tf32_hi(v.w));
            float4 lo = make_float4(v.x - hi.x, v.y - hi.y, v.z - hi.z, v.w - hi.w);
            *(float4*)&sWhi[n][k4 * 4] = hi;
            *(float4*)&sWlo[n][k4 * 4] = lo;
        }
        __syncthreads();

#pragma unroll
        for (int ks = 0; ks < 2; ks++) {
            int k0 = ks * 8;
            wmma::fragment<wmma::matrix_a, 16, 16, 8, wmma::precision::tf32, wmma::row_major> ahi, alo;
            wmma::load_matrix_sync(ahi, &sAhi[mt * 16][k0], 24);
            wmma::load_matrix_sync(alo, &sAlo[mt * 16][k0], 24);
#pragma unroll
            for (int nt = 0; nt < 4; nt++) {
                wmma::fragment<wmma::matrix_b, 16, 16, 8, wmma::precision::tf32, wmma::col_major> bhi, blo;
                wmma::load_matrix_sync(bhi, &sWhi[ng * 64 + nt * 16][k0], 24);
                wmma::load_matrix_sync(blo, &sWlo[ng * 64 + nt * 16][k0], 24);
                wmma::mma_sync(acc[nt], ahi, bhi, acc[nt]);
                wmma::mma_sync(acc[nt], alo, bhi, acc[nt]);
                wmma::mma_sync(acc[nt], ahi, blo, acc[nt]);
            }
        }
        __syncthreads();
    }

    // store raw accumulators (g_P padded to NP rows -> no guard needed)
#pragma unroll
    for (int nt = 0; nt < 4; nt++) {
        float* out = g_P + (size_t)(rowBase + mt * 16) * DD + ng * 64 + nt * 16;
        wmma::store_matrix_sync(out, acc[nt], DD, wmma::mem_row_major);
    }
}

// ---------------- pull aggregation + bias + ReLU ----------------------------
// one warp per node; lane owns cols lane*4..+3 (float4). Reads g_P.
// out_i = relu( sum_j w_ij * p_j  +  b * s_i )
template <bool TO_H>
__global__ __launch_bounds__(256) void k_pull(const float* __restrict__ bias,
                                              float* __restrict__ Ox) {
    int gw = (blockIdx.x * blockDim.x + threadIdx.x) >> 5;
    int lane = threadIdx.x & 31;
    if (gw >= NN) return;
    int s = g_off[gw];
    int e = g_off[gw + 1];
    const float4* __restrict__ Pb = (const float4*)g_P;
    float4 acc = make_float4(0.f, 0.f, 0.f, 0.f);
    int j = s;
    for (; j + 2 <= e; j += 2) {
        int2 e0 = g_edges[j];
        int2 e1 = g_edges[j + 1];
        float4 v0 = Pb[(size_t)e0.x * 32 + lane];
        float4 v1 = Pb[(size_t)e1.x * 32 + lane];
        float w0 = __int_as_float(e0.y);
        float w1 = __int_as_float(e1.y);
        acc.x += w0 * v0.x + w1 * v1.x;
        acc.y += w0 * v0.y + w1 * v1.y;
        acc.z += w0 * v0.z + w1 * v1.z;
        acc.w += w0 * v0.w + w1 * v1.w;
    }
    if (j < e) {
        int2 e0 = g_edges[j];
        float4 v0 = Pb[(size_t)e0.x * 32 + lane];
        float w0 = __int_as_float(e0.y);
        acc.x += w0 * v0.x;
        acc.y += w0 * v0.y;
        acc.z += w0 * v0.z;
        acc.w += w0 * v0.w;
    }
    float si = g_s[gw];
    float4 b4 = *(const float4*)(bias + lane * 4);
    float4 r = make_float4(fmaxf(acc.x + b4.x * si, 0.f),
                           fmaxf(acc.y + b4.y * si, 0.f),
                           fmaxf(acc.z + b4.z * si, 0.f),
                           fmaxf(acc.w + b4.w * si, 0.f));
    float4* Ob = TO_H ? (float4*)g_H : (float4*)Ox;
    Ob[(size_t)gw * 32 + lane] = r;
}

// ---------------- launch ----------------------------------------------------
extern "C" void kernel_launch(void* const* d_in, const int* in_sizes, int n_in,
                              void* d_out, int out_size) {
    const float* x  = (const float*)d_in[0];
    const void*  ei = d_in[1];                 // int32 or int64, detected on device
    const float* W1 = (const float*)d_in[2];
    const float* b1 = (const float*)d_in[3];
    const float* W2 = (const float*)d_in[4];
    const float* b2 = (const float*)d_in[5];
    const float* W3 = (const float*)d_in[6];
    const float* b3 = (const float*)d_in[7];
    float* out = (float*)d_out;

    const int TB = 256;
    // preprocess
    k_detect<<<1, 256>>>((const int*)ei);
    k_init  <<<(NN + TB - 1) / TB, TB>>>();
    k_count <<<(EE + TB - 1) / TB, TB>>>(ei);
    k_dis   <<<(NN + TB - 1) / TB, TB>>>();
    k_scan  <<<1, 1024>>>();
    k_fill  <<<(ET + TB - 1) / TB, TB>>>(ei);

    const int GB = (NN + 63) / 64;            // gemm blocks (1563)
    const int PB = (NN * 32 + TB - 1) / TB;   // pull blocks (warp per node)

    // layer 1: x -> P -> H
    k_gemm<false><<<GB, 256>>>(x, W1);
    k_pull<true><<<PB, 256>>>(b1, nullptr);
    // layer 2: H -> P -> H
    k_gemm<true><<<GB, 256>>>(nullptr, W2);
    k_pull<true><<<PB, 256>>>(b2, nullptr);
    // layer 3: H -> P -> out
    k_gemm<true><<<GB, 256>>>(nullptr, W3);
    k_pull<false><<<PB, 256>>>(b3, out);
}